// round 6
// baseline (speedup 1.0000x reference)
#include <cuda_runtime.h>
#include <cuda_bf16.h>
#include <stdint.h>

#define BB 8192
#define DD 2048
#define KK 512
#define QQ 8
#define CC (KK*QQ)

#define BM 128
#define BN 64
#define BKc 32
#define LDA 40              // padded smem row stride (bf16 elems) -> conflict-free LDS
#define NSTAGE 3
#define NKITER (DD/BKc)     // 64
#define NKT (KK/8)          // 64 k-tiles (8 components per gemm block)
#define STAGE_ELEMS ((BM+BN+8)*LDA)   // A tile + B tile + 8-row mu tile

// ---------------- scratch (static device globals; no allocation) -------------
__device__ __nv_bfloat16 g_Xbf[(size_t)BB*DD];      // 32 MB
__device__ __nv_bfloat16 g_PW[(size_t)CC*DD];       // 16 MB  psi_inv * W, row c=k*8+q
__device__ __nv_bfloat16 g_MuP[(size_t)KK*DD];      // 2 MB   psi_inv * mu
__device__ float g_psi_inv[DD];
__device__ float g_xpx[BB];
__device__ float g_pm[(size_t)NKT*BB];              // 2 MB  per-tile lse max
__device__ float g_ps[(size_t)NKT*BB];              // 2 MB  per-tile lse sum
__device__ float g_L[KK*64];                        // lower-tri, diag stores 1/L_ii
__device__ float g_vmu[KK*QQ];                      // W^T Psi^-1 mu
__device__ float g_c2[KK];                          // folded constants + log_pi
__device__ float g_logdet_psi;
__device__ float g_logpi[KK];
__device__ float g_nlogp[BB];

// ---------------- helpers ----------------------------------------------------
__device__ __forceinline__ float softplus_f(float x){
  return (x > 15.f) ? x : log1pf(expf(x));
}
__device__ __forceinline__ float wredsum(float v){
  #pragma unroll
  for (int o=16;o;o>>=1) v += __shfl_down_sync(0xffffffffu, v, o);
  return v;
}
__device__ __forceinline__ void cpasync16(void* s, const void* g){
  uint32_t sa = (uint32_t)__cvta_generic_to_shared(s);
  asm volatile("cp.async.cg.shared.global [%0], [%1], 16;\n" :: "r"(sa), "l"(g));
}

// ---------------- small prep kernels -----------------------------------------
__global__ void k_psi(const float* __restrict__ psi_rho){
  __shared__ float sh[8];
  int t = threadIdx.x;
  float acc = 0.f;
  for (int i=t;i<DD;i+=256){
    float p = softplus_f(psi_rho[i]) + 1e-5f;
    g_psi_inv[i] = 1.f/p;
    acc += logf(p);
  }
  acc = wredsum(acc);
  if ((t&31)==0) sh[t>>5] = acc;
  __syncthreads();
  if (t==0){ float s=0.f; for (int i=0;i<8;i++) s+=sh[i]; g_logdet_psi = s; }
}

__global__ void k_logpi(const float* __restrict__ pl){
  __shared__ float sh[16];
  __shared__ float s_m, s_l;
  int t = threadIdx.x;                 // 512 threads
  float v = pl[t];
  float m = v;
  #pragma unroll
  for (int o=16;o;o>>=1) m = fmaxf(m, __shfl_down_sync(0xffffffffu,m,o));
  if ((t&31)==0) sh[t>>5]=m;
  __syncthreads();
  if (t==0){ float mm=sh[0]; for(int i=1;i<16;i++) mm=fmaxf(mm,sh[i]); s_m=mm; }
  __syncthreads();
  float e = expf(v - s_m);
  float s = wredsum(e);
  if ((t&31)==0) sh[t>>5]=s;
  __syncthreads();
  if (t==0){ float ss=0.f; for(int i=0;i<16;i++) ss+=sh[i]; s_l = logf(ss); }
  __syncthreads();
  g_logpi[t] = v - s_m - s_l;
}

__global__ void __launch_bounds__(256) k_prepx(const float* __restrict__ x){
  __shared__ float sh[8];
  int b = blockIdx.x, t = threadIdx.x;
  const float4* __restrict__ xr = (const float4*)(x + (size_t)b*DD);
  uint2* xo = (uint2*)(g_Xbf + (size_t)b*DD);
  const float4* pv = (const float4*)g_psi_inv;
  float acc=0.f;
  for (int j=t;j<DD/4;j+=256){
    float4 xv = xr[j];
    float4 pi = pv[j];
    uint2 o;
    __nv_bfloat162 lo = __floats2bfloat162_rn(xv.x, xv.y);
    __nv_bfloat162 hi = __floats2bfloat162_rn(xv.z, xv.w);
    o.x = *(uint32_t*)&lo; o.y = *(uint32_t*)&hi;
    xo[j] = o;
    acc = fmaf(xv.x*xv.x, pi.x, acc);
    acc = fmaf(xv.y*xv.y, pi.y, acc);
    acc = fmaf(xv.z*xv.z, pi.z, acc);
    acc = fmaf(xv.w*xv.w, pi.w, acc);
  }
  acc = wredsum(acc);
  if ((t&31)==0) sh[t>>5]=acc;
  __syncthreads();
  if (t==0){ float s=0.f; for(int i=0;i<8;i++) s+=sh[i]; g_xpx[b]=s; }
}

#define TRI(i,j) ((i)*8+(j)-(((i)*((i)+1))>>1))
__global__ void __launch_bounds__(256) k_prepk(const float* __restrict__ mu,
     const float* __restrict__ dir_raw, const float* __restrict__ scale_rho){
  __shared__ __nv_bfloat16 s_pw[DD*QQ];   // 32 KB: bf16(psi_inv*w) cache
  __shared__ __nv_bfloat16 s_pm[DD];      // 4 KB:  bf16(psi_inv*mu) cache
  __shared__ float s_part[8][56];
  __shared__ float s_red[56];
  __shared__ float s_ws[8];
  int k = blockIdx.x, t = threadIdx.x, lane=t&31, w=t>>5;
  const float* __restrict__ dr  = dir_raw + (size_t)k*DD*QQ;
  const float* __restrict__ mur = mu + (size_t)k*DD;
  float gq[36], nsq[8], vm[8]; float mpm=0.f;
  #pragma unroll
  for (int i=0;i<36;i++) gq[i]=0.f;
  #pragma unroll
  for (int i=0;i<8;i++){ nsq[i]=0.f; vm[i]=0.f; }
  for (int d=t; d<DD; d+=256){
    float4 p0 = *(const float4*)(dr + (size_t)d*8);
    float4 p1 = *(const float4*)(dr + (size_t)d*8 + 4);
    float w8[8] = {p0.x,p0.y,p0.z,p0.w,p1.x,p1.y,p1.z,p1.w};
    float pinv = g_psi_inv[d];
    float md = mur[d];
    mpm = fmaf(md*md, pinv, mpm);
    float mp = md*pinv;
    s_pm[d] = __float2bfloat16(mp);
    float pw8[8];
    #pragma unroll
    for (int q=0;q<8;q++){
      nsq[q] = fmaf(w8[q],w8[q],nsq[q]);
      vm[q]  = fmaf(mp,w8[q],vm[q]);
      pw8[q] = pinv*w8[q];
      s_pw[d*8+q] = __float2bfloat16(pw8[q]);
    }
    #pragma unroll
    for (int i=0;i<8;i++){
      #pragma unroll
      for (int j=i;j<8;j++) gq[TRI(i,j)] = fmaf(pw8[i], w8[j], gq[TRI(i,j)]);
    }
  }
  // deterministic reduce: warp shuffles + fixed-order cross-warp sum
  #pragma unroll
  for (int i=0;i<36;i++){ float r = wredsum(gq[i]);  if(lane==0) s_part[w][i]=r; }
  #pragma unroll
  for (int q=0;q<8;q++){ float r = wredsum(nsq[q]); if(lane==0) s_part[w][36+q]=r; }
  #pragma unroll
  for (int q=0;q<8;q++){ float r = wredsum(vm[q]);  if(lane==0) s_part[w][44+q]=r; }
  { float r = wredsum(mpm); if(lane==0) s_part[w][52]=r; }
  __syncthreads();
  if (t<53){ float s=0.f; for(int wi=0;wi<8;wi++) s+=s_part[wi][t]; s_red[t]=s; }
  __syncthreads();
  if (t<8){
    float n = fmaxf(sqrtf(s_red[36+t]), 1e-5f);
    s_ws[t] = softplus_f(scale_rho[k*8+t]) / n;
  }
  __syncthreads();
  if (t<8) g_vmu[k*8+t] = s_ws[t]*s_red[44+t];
  if (t==0){
    float Mm[8][8], Lm[8][8], inv[8]; float ld=0.f;
    #pragma unroll
    for (int i=0;i<8;i++){
      #pragma unroll
      for (int j=i;j<8;j++){
        float m = s_ws[i]*s_ws[j]*s_red[TRI(i,j)] + ((i==j)?1.f:0.f);
        Mm[i][j]=m; Mm[j][i]=m;
      }
    }
    for (int i=0;i<8;i++){
      float s = Mm[i][i];
      for (int p=0;p<i;p++) s -= Lm[i][p]*Lm[i][p];
      float lii = sqrtf(s);
      ld += 2.f*logf(lii);
      inv[i] = 1.f/lii;
      Lm[i][i] = lii;
      for (int j=i+1;j<8;j++){
        float v2 = Mm[j][i];
        for (int p=0;p<i;p++) v2 -= Lm[j][p]*Lm[i][p];
        Lm[j][i] = v2*inv[i];
      }
    }
    for (int i=0;i<8;i++)
      for (int j=0;j<8;j++)
        g_L[k*64+i*8+j] = (i==j) ? inv[i] : (j<i ? Lm[i][j] : 0.f);
    g_c2[k] = -0.5f*((float)DD*1.8378770664093453f + g_logdet_psi + ld + s_red[52])
              + g_logpi[k];
  }
  __syncthreads();
  // phase 3: emit bf16 operands from the smem cache (no dir_raw/mu re-read)
  float ws[8];
  #pragma unroll
  for (int q=0;q<8;q++) ws[q] = s_ws[q];
  for (int d=t; d<DD; d+=256){
    #pragma unroll
    for (int q=0;q<8;q++){
      float pw = __bfloat162float(s_pw[d*8+q]);
      g_PW[(size_t)(k*8+q)*DD + d] = __float2bfloat16(pw*ws[q]);
    }
    g_MuP[(size_t)k*DD + d] = s_pm[d];
  }
}

// ---------------- fused GEMM: V + cross + solve + ll + tile-lse --------------
// Tile: 128 rows (samples) x 64 cols (8 components x q=8), plus an 8-row
// psi_inv*mu micro-tile for the same 8 components -> cross term in-tile.
// Epilogue emits a per-(tile,sample) logsumexp partial (max, sumexp) instead
// of materializing ll -> 8x less traffic than storing ll.
__global__ void __launch_bounds__(256) k_gemm(){
  __shared__ __align__(16) __nv_bfloat16 smem[NSTAGE*STAGE_ELEMS];   // 48000 B
  int t = threadIdx.x, lane = t&31, warp = t>>5;
  int m0 = blockIdx.x*BM;
  int n0 = blockIdx.y*BN;
  int k0 = n0>>3;                  // first of 8 components in this tile
  const __nv_bfloat16* __restrict__ gA = g_Xbf + (size_t)m0*DD;
  const __nv_bfloat16* __restrict__ gB = g_PW  + (size_t)n0*DD;
  const __nv_bfloat16* __restrict__ gM = g_MuP + (size_t)k0*DD;

  auto load_stage = [&](int st, int kt){
    __nv_bfloat16* sA = smem + st*STAGE_ELEMS;
    __nv_bfloat16* sB = sA + BM*LDA;
    __nv_bfloat16* sM = sB + BN*LDA;
    int kc = kt*BKc;
    int cs = (t&3)*8;
    #pragma unroll
    for (int i=0;i<2;i++){
      int r = (t>>2) + i*64;
      cpasync16(sA + r*LDA + cs, gA + (size_t)r*DD + kc + cs);
    }
    cpasync16(sB + (t>>2)*LDA + cs, gB + (size_t)(t>>2)*DD + kc + cs);
    if (t < 32)
      cpasync16(sM + (t>>2)*LDA + cs, gM + (size_t)(t>>2)*DD + kc + cs);
  };

  float acc[2][4][4];
  float accm[2][4];                // cross accum (wn==0 warps only)
  #pragma unroll
  for (int a=0;a<2;a++){
    #pragma unroll
    for (int b2=0;b2<4;b2++){
      #pragma unroll
      for (int c=0;c<4;c++) acc[a][b2][c]=0.f;
      accm[a][b2]=0.f;
    }
  }

  load_stage(0,0); asm volatile("cp.async.commit_group;\n" ::: "memory");
  load_stage(1,1); asm volatile("cp.async.commit_group;\n" ::: "memory");

  int g = lane>>2, tg = lane&3;
  int wm = (warp>>1)*32, wn = (warp&1)*32;
  bool do_mu = (wn==0);

  int st = 0;
  for (int kt=0; kt<NKITER; kt++){
    if (kt == NKITER-1) asm volatile("cp.async.wait_group 0;\n" ::: "memory");
    else                asm volatile("cp.async.wait_group 1;\n" ::: "memory");
    __syncthreads();
    if (kt+2 < NKITER){
      int st2 = st+2; if (st2>=NSTAGE) st2-=NSTAGE;
      load_stage(st2, kt+2);
      asm volatile("cp.async.commit_group;\n" ::: "memory");
    }
    const __nv_bfloat16* sA = smem + st*STAGE_ELEMS;
    const __nv_bfloat16* sB = sA + BM*LDA;
    const __nv_bfloat16* sM = sB + BN*LDA;
    #pragma unroll
    for (int ks=0;ks<2;ks++){
      int kb = ks*16 + 2*tg;
      uint32_t a[2][4], bf[4][2];
      #pragma unroll
      for (int mi=0;mi<2;mi++){
        const __nv_bfloat16* p = sA + (wm+mi*16+g)*LDA + kb;
        a[mi][0] = *(const uint32_t*)(p);
        a[mi][1] = *(const uint32_t*)(p + 8*LDA);
        a[mi][2] = *(const uint32_t*)(p + 8);
        a[mi][3] = *(const uint32_t*)(p + 8*LDA + 8);
      }
      #pragma unroll
      for (int ni=0;ni<4;ni++){
        const __nv_bfloat16* p = sB + (wn+ni*8+g)*LDA + kb;
        bf[ni][0] = *(const uint32_t*)(p);
        bf[ni][1] = *(const uint32_t*)(p + 8);
      }
      #pragma unroll
      for (int mi=0;mi<2;mi++)
        #pragma unroll
        for (int ni=0;ni<4;ni++){
          asm volatile(
            "mma.sync.aligned.m16n8k16.row.col.f32.bf16.bf16.f32 "
            "{%0,%1,%2,%3}, {%4,%5,%6,%7}, {%8,%9}, {%0,%1,%2,%3};\n"
            : "+f"(acc[mi][ni][0]), "+f"(acc[mi][ni][1]),
              "+f"(acc[mi][ni][2]), "+f"(acc[mi][ni][3])
            : "r"(a[mi][0]), "r"(a[mi][1]), "r"(a[mi][2]), "r"(a[mi][3]),
              "r"(bf[ni][0]), "r"(bf[ni][1]));
        }
      if (do_mu){
        const __nv_bfloat16* p = sM + g*LDA + kb;
        uint32_t bm0 = *(const uint32_t*)(p);
        uint32_t bm1 = *(const uint32_t*)(p + 8);
        #pragma unroll
        for (int mi=0;mi<2;mi++){
          asm volatile(
            "mma.sync.aligned.m16n8k16.row.col.f32.bf16.bf16.f32 "
            "{%0,%1,%2,%3}, {%4,%5,%6,%7}, {%8,%9}, {%0,%1,%2,%3};\n"
            : "+f"(accm[mi][0]), "+f"(accm[mi][1]),
              "+f"(accm[mi][2]), "+f"(accm[mi][3])
            : "r"(a[mi][0]), "r"(a[mi][1]), "r"(a[mi][2]), "r"(a[mi][3]),
              "r"(bm0), "r"(bm1));
        }
      }
    }
    st++; if (st>=NSTAGE) st=0;
  }

  // -------- epilogue: reorganize V tile + cross through smem -----------------
  __syncthreads();
  float* sC  = (float*)smem;                 // 128 x 65
  float* sMu = sC + BM*65;                   // 128 x 9 (cross per row x 8 k's)
  float* sL  = sMu + BM*9;                   // 8 k's x 64
  float* sVmu= sL + 512;
  float* sC2 = sVmu + 64;
  float* sm2 = sC2 + 8;                      // 256 lse partial maxes
  float* ss2 = sm2 + 256;                    // 256 lse partial sums
  #pragma unroll
  for (int mi=0;mi<2;mi++){
    #pragma unroll
    for (int ni=0;ni<4;ni++){
      int r = wm + mi*16 + g;
      int c = wn + ni*8 + 2*tg;
      sC[r*65+c]       = acc[mi][ni][0];
      sC[r*65+c+1]     = acc[mi][ni][1];
      sC[(r+8)*65+c]   = acc[mi][ni][2];
      sC[(r+8)*65+c+1] = acc[mi][ni][3];
    }
  }
  if (do_mu){
    #pragma unroll
    for (int mi=0;mi<2;mi++){
      int r = wm + mi*16 + g;
      int c = 2*tg;
      sMu[r*9+c]       = accm[mi][0];
      sMu[r*9+c+1]     = accm[mi][1];
      sMu[(r+8)*9+c]   = accm[mi][2];
      sMu[(r+8)*9+c+1] = accm[mi][3];
    }
  }
  for (int i=t;i<512;i+=256) sL[i] = g_L[(size_t)(k0+(i>>6))*64 + (i&63)];
  if (t<64) sVmu[t] = g_vmu[k0*8+t];
  if (t<8)  sC2[t]  = g_c2[k0+t];
  __syncthreads();

  // thread t owns row = t&127 and kk = (t>>7)+2i, i=0..3  (4 solves/thread)
  int row = t&127, half = t>>7;
  int b = m0 + row;
  float xpxh = 0.5f*g_xpx[b];
  float ll4[4];
  #pragma unroll
  for (int i=0;i<4;i++){
    int kk = half + 2*i;
    const float* Lk = sL + kk*64;
    float v[8], y[8], z[8];
    #pragma unroll
    for (int q=0;q<8;q++) v[q] = sC[row*65 + kk*8 + q] - sVmu[kk*8+q];
    #pragma unroll
    for (int ii=0;ii<8;ii++){
      float s = v[ii];
      #pragma unroll
      for (int j=0;j<ii;j++) s -= Lk[ii*8+j]*y[j];
      y[ii] = s*Lk[ii*8+ii];                   // diag holds 1/L_ii
    }
    float ve = 0.f;
    #pragma unroll
    for (int ii=7;ii>=0;ii--){
      float s = y[ii];
      #pragma unroll
      for (int j=ii+1;j<8;j++) s -= Lk[j*8+ii]*z[j];
      z[ii] = s*Lk[ii*8+ii];
      ve = fmaf(v[ii], z[ii], ve);
    }
    ll4[i] = sC2[kk] - xpxh + sMu[row*9+kk] + 0.5f*ve;
  }
  // per-thread lse over its 4 kk's, then pairwise combine across halves
  float mloc = fmaxf(fmaxf(ll4[0],ll4[1]), fmaxf(ll4[2],ll4[3]));
  float sloc = expf(ll4[0]-mloc)+expf(ll4[1]-mloc)+expf(ll4[2]-mloc)+expf(ll4[3]-mloc);
  sm2[t]=mloc; ss2[t]=sloc;
  __syncthreads();
  if (half==0){
    float ma=sm2[t], mb_=sm2[t+128];
    float sa=ss2[t], sb_=ss2[t+128];
    float M = fmaxf(ma, mb_);
    float S = sa*expf(ma-M) + sb_*expf(mb_-M);
    g_pm[(size_t)blockIdx.y*BB + b] = M;
    g_ps[(size_t)blockIdx.y*BB + b] = S;
  }
}

// ---------------- merge per-tile lse partials + final mean -------------------
__global__ void k_lse(){
  int b = blockIdx.x*256 + threadIdx.x;
  float m = -1e30f, s = 0.f;
  #pragma unroll 4
  for (int tile=0; tile<NKT; tile++){
    float pm = g_pm[(size_t)tile*BB + b];
    float ps = g_ps[(size_t)tile*BB + b];
    if (pm > m){ s = s*expf(m - pm) + ps; m = pm; }
    else         s += ps*expf(pm - m);
  }
  g_nlogp[b] = -(m + logf(s));
}

__global__ void k_final(float* __restrict__ out){
  __shared__ double sh[8];
  int t = threadIdx.x;
  double acc = 0.0;
  for (int i=t;i<BB;i+=256) acc += (double)g_nlogp[i];
  #pragma unroll
  for (int o=16;o;o>>=1) acc += __shfl_down_sync(0xffffffffu, acc, o);
  if ((t&31)==0) sh[t>>5]=acc;
  __syncthreads();
  if (t==0){
    double s=0.0; for (int i=0;i<8;i++) s+=sh[i];
    out[0] = (float)(s/(double)BB);
  }
}

// ---------------- launch ------------------------------------------------------
extern "C" void kernel_launch(void* const* d_in, const int* in_sizes, int n_in,
                              void* d_out, int out_size){
  const float* x         = (const float*)d_in[0];
  const float* mu        = (const float*)d_in[1];
  const float* dir_raw   = (const float*)d_in[2];
  const float* scale_rho = (const float*)d_in[3];
  const float* psi_rho   = (const float*)d_in[4];
  const float* pi_logits = (const float*)d_in[5];

  k_psi  <<<1,256>>>(psi_rho);
  k_logpi<<<1,512>>>(pi_logits);
  k_prepx<<<BB,256>>>(x);
  k_prepk<<<KK,256>>>(mu, dir_raw, scale_rho);
  k_gemm <<<dim3(BB/BM, CC/BN),256>>>();     // fused V+cross GEMM + solve + ll + tile-lse
  k_lse  <<<BB/256,256>>>();
  k_final<<<1,256>>>((float*)d_out);
}